// round 11
// baseline (speedup 1.0000x reference)
#include <cuda_runtime.h>
#include <cuda_bf16.h>
#include <math_constants.h>

// Problem constants
#define B 2
#define L 1024
#define E 1024
#define H 16
#define NT (B*L)          // 2048 tokens
#define LOG2E 1.4426950408889634f
#define KSPLIT 8

typedef unsigned long long u64;

// -------- scratch (static __device__, no allocations) --------
__device__ float2 g_stats[NT];                   // per-token (mu, rstd)
__device__ float  g_projp[KSPLIT][NT * 240];     // QKV projection partials
__device__ float4 g_Q[B*H*L * 2];                // per (b,h,i): (alpha'*Qr, q2), (qd, -beta')
// j-pair-interleaved K/V: per bh, 6 arrays of 512 float4:
// arr0=(krx0,krx1,kry0,kry1) arr1=(krz,k2) arr2=(kdx,kdy) arr3=(kdz,mp) arr4=(vx,vy) arr5=(vz,pad)
__device__ float4 g_K2[B*H * 6 * (L/2)];
__device__ float  g_O[NT * H * 3];               // attention output (B,L,H,3)

// ---------------- f32x2 helpers ----------------
__device__ __forceinline__ u64 pk2(float lo, float hi)
{ u64 r; asm("mov.b64 %0, {%1,%2};" : "=l"(r) : "f"(lo), "f"(hi)); return r; }
__device__ __forceinline__ u64 bc2(float v) { return pk2(v, v); }
__device__ __forceinline__ void up2(float &lo, float &hi, u64 v)
{ asm("mov.b64 {%0,%1}, %2;" : "=f"(lo), "=f"(hi) : "l"(v)); }
__device__ __forceinline__ u64 fma2(u64 a, u64 b, u64 c)
{ u64 d; asm("fma.rn.f32x2 %0, %1, %2, %3;" : "=l"(d) : "l"(a), "l"(b), "l"(c)); return d; }
__device__ __forceinline__ u64 add2(u64 a, u64 b)
{ u64 d; asm("add.rn.f32x2 %0, %1, %2;" : "=l"(d) : "l"(a), "l"(b)); return d; }

// ============================================================
// K1: LayerNorm STATS ONLY (mu, rstd per token)
// ============================================================
__global__ void __launch_bounds__(256) ln_stats(const float* __restrict__ x)
{
    int t   = blockIdx.x;
    int tid = threadIdx.x;
    const float4* xr = (const float4*)(x + (size_t)t * E);
    float4 v = xr[tid];
    float s  = v.x + v.y + v.z + v.w;
    float ss = v.x*v.x + v.y*v.y + v.z*v.z + v.w*v.w;
    #pragma unroll
    for (int o = 16; o; o >>= 1) {
        s  += __shfl_xor_sync(0xFFFFFFFFu, s,  o);
        ss += __shfl_xor_sync(0xFFFFFFFFu, ss, o);
    }
    __shared__ float sm[8], sm2[8];
    if ((tid & 31) == 0) { sm[tid >> 5] = s; sm2[tid >> 5] = ss; }
    __syncthreads();
    if (tid == 0) {
        float S = 0.f, SS = 0.f;
        #pragma unroll
        for (int i = 0; i < 8; i++) { S += sm[i]; SS += sm2[i]; }
        float mu  = S * (1.0f / E);
        float var = SS * (1.0f / E) - mu * mu;
        g_stats[t] = make_float2(mu, rsqrtf(var + 1e-5f));
    }
}

// ============================================================
// K2: QKV GEMM, f32x2, conflict-free staging, LN fused. (proven R10)
// ============================================================
__global__ void __launch_bounds__(128) qkv_gemm(const float* __restrict__ x,
                                                const float* __restrict__ gamma,
                                                const float* __restrict__ beta,
                                                const float* __restrict__ W)
{
    __shared__ float As[16 * 64];
    __shared__ float Bs[16 * 98];

    int bm = blockIdx.x * 64;
    int bn = blockIdx.y * 48;
    int kh = blockIdx.z;
    int t  = threadIdx.x;
    int ty2 = (t >> 4) * 2;
    int tx = t & 15;

    u64 acc[4][3];
    #pragma unroll
    for (int i = 0; i < 4; i++)
        #pragma unroll
        for (int c = 0; c < 3; c++) acc[i][c] = 0ull;

    int arow0 = t >> 2;
    int akc   = (t & 3) * 4;
    int aq2   = (t & 3) << 1;

    int bk  = t >> 3;
    int bcf = (t & 7) * 6;

    float2 st[2];
    st[0] = g_stats[bm + arow0];
    st[1] = g_stats[bm + arow0 + 32];

    const int KQ = 1024 / KSPLIT;
    for (int k0 = kh * KQ; k0 < kh * KQ + KQ; k0 += 16) {
        float4 ga = *(const float4*)(gamma + k0 + akc);
        float4 bt = *(const float4*)(beta  + k0 + akc);
        #pragma unroll
        for (int i = 0; i < 2; i++) {
            int row = arow0 + 32 * i;
            float4 av = *(const float4*)(x + (size_t)(bm + row) * E + k0 + akc);
            float mu = st[i].x, rs = st[i].y;
            int gofs = (((row >> 2) ^ aq2) << 2) + (row & 3);
            As[(akc + 0) * 64 + gofs] = fmaf((av.x - mu) * rs, ga.x, bt.x);
            As[(akc + 1) * 64 + gofs] = fmaf((av.y - mu) * rs, ga.y, bt.y);
            As[(akc + 2) * 64 + gofs] = fmaf((av.z - mu) * rs, ga.z, bt.z);
            As[(akc + 3) * 64 + gofs] = fmaf((av.w - mu) * rs, ga.w, bt.w);
        }
        {
            const float* wp = W + (size_t)(k0 + bk) * 240 + bn + bcf;
            float2 b0 = *(const float2*)(wp + 0);
            float2 b1 = *(const float2*)(wp + 2);
            float2 b2 = *(const float2*)(wp + 4);
            u64* bs = (u64*)&Bs[bk * 98 + bcf * 2];
            bs[0] = bc2(b0.x); bs[1] = bc2(b0.y);
            bs[2] = bc2(b1.x); bs[3] = bc2(b1.y);
            bs[4] = bc2(b2.x); bs[5] = bc2(b2.y);
        }
        __syncthreads();
        #pragma unroll
        for (int kk = 0; kk < 16; kk++) {
            const int q2s = (kk >> 2) << 1;
            const float* arow = &As[kk * 64 + ((ty2 ^ q2s) << 2)];
            ulonglong2 a01 = *(const ulonglong2*)(arow);
            ulonglong2 a23 = *(const ulonglong2*)(arow + 4);
            const float* brow = &Bs[kk * 98 + tx * 6];
            u64 b0 = *(const u64*)(brow + 0);
            u64 b1 = *(const u64*)(brow + 2);
            u64 b2 = *(const u64*)(brow + 4);
            acc[0][0]=fma2(a01.x,b0,acc[0][0]); acc[0][1]=fma2(a01.x,b1,acc[0][1]); acc[0][2]=fma2(a01.x,b2,acc[0][2]);
            acc[1][0]=fma2(a01.y,b0,acc[1][0]); acc[1][1]=fma2(a01.y,b1,acc[1][1]); acc[1][2]=fma2(a01.y,b2,acc[1][2]);
            acc[2][0]=fma2(a23.x,b0,acc[2][0]); acc[2][1]=fma2(a23.x,b1,acc[2][1]); acc[2][2]=fma2(a23.x,b2,acc[2][2]);
            acc[3][0]=fma2(a23.y,b0,acc[3][0]); acc[3][1]=fma2(a23.y,b1,acc[3][1]); acc[3][2]=fma2(a23.y,b2,acc[3][2]);
        }
        __syncthreads();
    }

    float* out = g_projp[kh];
    int ty = t >> 4;
    #pragma unroll
    for (int i = 0; i < 4; i++) {
        int row = bm + ty * 8 + 2 * i;
        #pragma unroll
        for (int c = 0; c < 3; c++) {
            float lo, hi;
            up2(lo, hi, acc[i][c]);
            int col = bn + tx * 3 + c;
            out[(size_t)row * 240 + col]       = lo;
            out[(size_t)(row + 1) * 240 + col] = hi;
        }
    }
}

// ============================================================
// K2b: rotate + translate + pack (token,head); emits Q (as before)
// and the j-pair interleaved K layout via smem transpose.
// block = 16 tokens x 16 heads; grid = NT/16 = 128.
// ============================================================
__device__ __forceinline__ float softplus_f(float x)
{
    return (x > 20.f) ? x : log1pf(__expf(x));
}

__global__ void __launch_bounds__(256) pack_kernel(const float* __restrict__ rot,
                                                   const float* __restrict__ trans,
                                                   const unsigned char* __restrict__ mask,
                                                   const float* __restrict__ r_scale,
                                                   const float* __restrict__ d_scale)
{
    __shared__ float sp[16 * 16 * 12];   // [h][t_loc][comp0..11], 12KB
    int tid = threadIdx.x;
    int t0  = blockIdx.x * 16;
    int t_loc = tid >> 4;
    int h = tid & 15;
    int t = t0 + t_loc;

    float R[9];
    #pragma unroll
    for (int i = 0; i < 9; i++) R[i] = rot[t*9 + i];
    float T0 = trans[t*3+0], T1 = trans[t*3+1], T2 = trans[t*3+2];

    float y[5][3];
    #pragma unroll
    for (int f = 0; f < 5; f++) {
        int o = f*48 + h*3;
        float v0 = 0.f, v1 = 0.f, v2 = 0.f;
        #pragma unroll
        for (int q = 0; q < KSPLIT; q++) {
            const float* P = g_projp[q] + (size_t)t * 240;
            v0 += P[o+0]; v1 += P[o+1]; v2 += P[o+2];
        }
        y[f][0] = R[0]*v0 + R[1]*v1 + R[2]*v2;
        y[f][1] = R[3]*v0 + R[4]*v1 + R[5]*v2;
        y[f][2] = R[6]*v0 + R[7]*v1 + R[8]*v2;
    }
    const float scale = 0.5773502691896258f;      // 3^-0.5
    float alpha = softplus_f(r_scale[h]) * scale * LOG2E;
    float nbeta = -softplus_f(d_scale[h]) * scale * LOG2E;

    float qd0 = y[2][0] + T0, qd1 = y[2][1] + T1, qd2 = y[2][2] + T2;
    float q2  = qd0*qd0 + qd1*qd1 + qd2*qd2;
    float kd0 = y[3][0] + T0, kd1 = y[3][1] + T1, kd2 = y[3][2] + T2;
    float k2  = kd0*kd0 + kd1*kd1 + kd2*kd2;

    int b = t >> 10, l = t & 1023;
    int base = (b*H + h) * L + l;

    g_Q[base*2 + 0] = make_float4(alpha*y[0][0], alpha*y[0][1], alpha*y[0][2], q2);
    g_Q[base*2 + 1] = make_float4(qd0, qd1, qd2, nbeta);

    float mpen = mask[t] ? -2.0e9f : 0.f;   // log2 units; EX2 -> 0
    float* spr = &sp[(h * 16 + t_loc) * 12];
    spr[0]  = y[1][0]; spr[1] = y[1][1]; spr[2] = y[1][2]; spr[3] = k2;
    spr[4]  = -2.f*kd0; spr[5] = -2.f*kd1; spr[6] = -2.f*kd2; spr[7] = mpen;
    spr[8]  = y[4][0]; spr[9] = y[4][1]; spr[10] = y[4][2]; spr[11] = 0.f;
    __syncthreads();

    // store phase: 16 bh x 6 arrays x 8 jp = 768 float4 (coalesced 128B runs)
    int bb  = t0 >> 10;
    int jp0 = (t0 & 1023) >> 1;
    #pragma unroll
    for (int i = tid; i < 768; i += 256) {
        int hh  = i / 48;
        int rem = i % 48;
        int arr = rem >> 3;
        int jpl = rem & 7;
        int a2  = arr * 2;
        const float* s0 = &sp[(hh * 16 + 2*jpl + 0) * 12];
        const float* s1 = &sp[(hh * 16 + 2*jpl + 1) * 12];
        float4 v;
        v.x = s0[a2];     v.y = s1[a2];
        v.z = s0[a2 + 1]; v.w = s1[a2 + 1];
        g_K2[((size_t)(bb * H + hh) * 6 + arr) * (L/2) + jp0 + jpl] = v;
    }
}

// ============================================================
// K3: flash attention, f32x2 packed over J-PAIRS (K operands arrive
// pre-packed from smem; Q broadcasts hoisted). 8 warps x 4 rows.
// grid (B*H, L/32). smem 48KB, 2 blocks/SM.
// ============================================================
__global__ void __launch_bounds__(256, 2) attn_kernel()
{
    __shared__ float4 sk[6 * (L/2)];   // 48KB: 6 arrays x 512 jp

    int bh    = blockIdx.x;
    int itile = blockIdx.y;

    const float4* Ksrc = g_K2 + (size_t)bh * 6 * (L/2);
    #pragma unroll
    for (int i = 0; i < 12; i++) sk[threadIdx.x + 256 * i] = Ksrc[threadIdx.x + 256 * i];
    __syncthreads();

    int warp = threadIdx.x >> 5, lane = threadIdx.x & 31;
    int rbase = itile * 32 + warp * 4;

    const float4* Qsrc = g_Q + (size_t)(bh * L + rbase) * 2;
    u64 QRX[4], QRY[4], QRZ[4], Q2[4], QDX[4], QDY[4], QDZ[4];
    u64 S[4], A0[4], A1[4], A2[4];
    u64 NB;
    #pragma unroll
    for (int r = 0; r < 4; r++) {
        float4 a = Qsrc[r*2];
        float4 bq = Qsrc[r*2 + 1];
        QRX[r] = bc2(a.x); QRY[r] = bc2(a.y); QRZ[r] = bc2(a.z); Q2[r] = bc2(a.w);
        QDX[r] = bc2(bq.x); QDY[r] = bc2(bq.y); QDZ[r] = bc2(bq.z);
        if (r == 0) NB = bc2(bq.w);
        S[r] = 0ull; A0[r] = 0ull; A1[r] = 0ull; A2[r] = 0ull;
    }

    #pragma unroll 2
    for (int jj = 0; jj < 16; jj++) {
        int jp = jj * 32 + lane;
        ulonglong2 w0 = *(const ulonglong2*)&sk[0*512 + jp];   // KRX, KRY
        ulonglong2 w1 = *(const ulonglong2*)&sk[1*512 + jp];   // KRZ, K2
        ulonglong2 w2 = *(const ulonglong2*)&sk[2*512 + jp];   // KDX, KDY
        ulonglong2 w3 = *(const ulonglong2*)&sk[3*512 + jp];   // KDZ, MP
        ulonglong2 w4 = *(const ulonglong2*)&sk[4*512 + jp];   // VX, VY
        ulonglong2 w5 = *(const ulonglong2*)&sk[5*512 + jp];   // VZ, pad
        #pragma unroll
        for (int r = 0; r < 4; r++) {
            u64 t1 = fma2(QRX[r], w0.x, w3.y);    // rot dot + mask penalty
            t1 = fma2(QRY[r], w0.y, t1);
            t1 = fma2(QRZ[r], w1.x, t1);
            u64 d2 = add2(Q2[r], w1.y);           // q2 + k2
            d2 = fma2(QDX[r], w2.x, d2);          // K side holds -2*kd
            d2 = fma2(QDY[r], w2.y, d2);
            d2 = fma2(QDZ[r], w3.x, d2);
            float d2a, d2b;
            up2(d2a, d2b, d2);
            float da, db, pa, pb;
            float ada = fabsf(d2a), adb = fabsf(d2b);
            asm("sqrt.approx.f32 %0, %1;" : "=f"(da) : "f"(ada));
            asm("sqrt.approx.f32 %0, %1;" : "=f"(db) : "f"(adb));
            u64 DD = pk2(da, db);
            u64 ARG = fma2(NB, DD, t1);
            float arga, argb;
            up2(arga, argb, ARG);
            asm("ex2.approx.f32 %0, %1;" : "=f"(pa) : "f"(arga));
            asm("ex2.approx.f32 %0, %1;" : "=f"(pb) : "f"(argb));
            u64 P = pk2(pa, pb);
            S [r] = add2(S[r], P);
            A0[r] = fma2(P, w4.x, A0[r]);
            A1[r] = fma2(P, w4.y, A1[r]);
            A2[r] = fma2(P, w5.x, A2[r]);
        }
    }

    // collapse j-pair halves, then cross-lane sum reduce
    int b = bh >> 4, h = bh & 15;
    #pragma unroll
    for (int r = 0; r < 4; r++) {
        float s0, s1, x0, x1, y0, y1, z0, z1;
        up2(s0, s1, S[r]); up2(x0, x1, A0[r]); up2(y0, y1, A1[r]); up2(z0, z1, A2[r]);
        float s = s0 + s1, xx = x0 + x1, yy = y0 + y1, zz = z0 + z1;
        #pragma unroll
        for (int o = 16; o; o >>= 1) {
            s  += __shfl_xor_sync(0xFFFFFFFFu, s,  o);
            xx += __shfl_xor_sync(0xFFFFFFFFu, xx, o);
            yy += __shfl_xor_sync(0xFFFFFFFFu, yy, o);
            zz += __shfl_xor_sync(0xFFFFFFFFu, zz, o);
        }
        if (lane == 0) {
            float inv;
            asm("rcp.approx.f32 %0, %1;" : "=f"(inv) : "f"(s));
            int row = rbase + r;
            float* op = g_O + ((size_t)(b * L + row) * H + h) * 3;
            op[0] = xx * inv; op[1] = yy * inv; op[2] = zz * inv;
        }
    }
}

// ============================================================
// K4: rotate back (R^T) + output GEMM (48 -> 1024) + bias, f32x2
// 16 tokens per block, 256 threads.  (proven R10)
// ============================================================
__global__ void __launch_bounds__(256) out_kernel(const float* __restrict__ rot,
                                                  const float* __restrict__ Wout,
                                                  const float* __restrict__ bout,
                                                  float* __restrict__ out)
{
    __shared__ float so[48][16];
    int t0  = blockIdx.x * 16;
    int tid = threadIdx.x;

    {
        int tt = tid >> 4, h = tid & 15;
        int t = t0 + tt;
        const float* op = g_O + ((size_t)t * H + h) * 3;
        float R0 = rot[t*9+0], R1 = rot[t*9+1], R2 = rot[t*9+2];
        float R3 = rot[t*9+3], R4 = rot[t*9+4], R5 = rot[t*9+5];
        float R6 = rot[t*9+6], R7 = rot[t*9+7], R8 = rot[t*9+8];
        float o0 = op[0], o1 = op[1], o2 = op[2];
        so[h*3+0][tt] = R0*o0 + R3*o1 + R6*o2;
        so[h*3+1][tt] = R1*o0 + R4*o1 + R7*o2;
        so[h*3+2][tt] = R2*o0 + R5*o1 + R8*o2;
    }
    __syncthreads();

    int e0 = tid;
    u64 acc[8][4];
    #pragma unroll
    for (int c = 0; c < 4; c++) {
        float bb = bout[e0 + 256*c];
        u64 bb2 = bc2(bb);
        #pragma unroll
        for (int tp = 0; tp < 8; tp++) acc[tp][c] = bb2;
    }

    #pragma unroll 4
    for (int k = 0; k < 48; k++) {
        u64 w2[4];
        #pragma unroll
        for (int c = 0; c < 4; c++) w2[c] = bc2(Wout[(size_t)k*E + e0 + 256*c]);
        const u64* sop = (const u64*)&so[k][0];
        #pragma unroll
        for (int tp = 0; tp < 8; tp++) {
            u64 sv = sop[tp];
            acc[tp][0] = fma2(sv, w2[0], acc[tp][0]);
            acc[tp][1] = fma2(sv, w2[1], acc[tp][1]);
            acc[tp][2] = fma2(sv, w2[2], acc[tp][2]);
            acc[tp][3] = fma2(sv, w2[3], acc[tp][3]);
        }
    }
    #pragma unroll
    for (int tp = 0; tp < 8; tp++) {
        float* orow0 = out + (size_t)(t0 + 2*tp) * E;
        float* orow1 = out + (size_t)(t0 + 2*tp + 1) * E;
        #pragma unroll
        for (int c = 0; c < 4; c++) {
            float lo, hi;
            up2(lo, hi, acc[tp][c]);
            orow0[e0 + 256*c] = lo;
            orow1[e0 + 256*c] = hi;
        }
    }
}

// ============================================================
extern "C" void kernel_launch(void* const* d_in, const int* in_sizes, int n_in,
                              void* d_out, int out_size)
{
    const float*         x       = (const float*)d_in[0];
    const float*         rot     = (const float*)d_in[1];
    const float*         trans   = (const float*)d_in[2];
    const unsigned char* mask    = (const unsigned char*)d_in[3];
    const float*         Wqkv    = (const float*)d_in[4];
    const float*         Wout    = (const float*)d_in[5];
    const float*         bout    = (const float*)d_in[6];
    const float*         gamma   = (const float*)d_in[7];
    const float*         beta    = (const float*)d_in[8];
    const float*         r_scale = (const float*)d_in[9];
    const float*         d_scale = (const float*)d_in[10];
    float* out = (float*)d_out;

    ln_stats<<<NT, 256>>>(x);
    qkv_gemm<<<dim3(NT/64, 5, KSPLIT), 128>>>(x, gamma, beta, Wqkv);
    pack_kernel<<<NT/16, 256>>>(rot, trans, mask, r_scale, d_scale);
    attn_kernel<<<dim3(B*H, L/32), 256>>>();
    out_kernel<<<NT/16, 256>>>(rot, Wout, bout, out);
}